// round 3
// baseline (speedup 1.0000x reference)
#include <cuda_runtime.h>
#include <math_constants.h>

// ChamferLoss: B=8, N=M=4096, D=3, fp32 in, scalar fp32 out.
// d2' = -2*dot(q,r) + rsq   (qsq folded in AFTER the min)
// fma.rn.f32x2 packs TWO CANDIDATES per instruction (query duplicated in regs).
// PTS=1 -> 2048 warps total (3.5/SMSP) to hide FFMA/LDS latency.

#define B_DIM 8
#define N_PTS 4096
#define TPB   128       // threads per block (4 warps), 1 query point per thread
#define TILE  1024      // candidate points per shared tile (512 packed pairs)
#define NPAIR (TILE / 2)
#define EPS   1e-8f

typedef unsigned long long u64;

__device__ __forceinline__ u64 ffma2(u64 a, u64 b, u64 c) {
    u64 d;
    asm("fma.rn.f32x2 %0, %1, %2, %3;" : "=l"(d) : "l"(a), "l"(b), "l"(c));
    return d;
}
__device__ __forceinline__ u64 pack2(float lo, float hi) {
    u64 d;
    asm("mov.b64 %0, {%1, %2};" : "=l"(d) : "f"(lo), "f"(hi));
    return d;
}
__device__ __forceinline__ float2 unpack2(u64 v) {
    float2 f;
    asm("mov.b64 {%0, %1}, %2;" : "=f"(f.x), "=f"(f.y) : "l"(v));
    return f;
}

__global__ void zero_out_kernel(float* out) { out[0] = 0.0f; }

__global__ __launch_bounds__(TPB) void chamfer_kernel(
    const float* __restrict__ x1, const float* __restrict__ y1,
    float* __restrict__ out, float scale)
{
    // sA[k] = { (c0_j, c0_j1), (c1_j, c1_j1) }   sB[k] = { (c2_j, c2_j1), (cr_j, cr_j1) }
    // where j = 2k, j1 = 2k+1,  c = -2*r coord,  cr = |r|^2
    __shared__ ulonglong2 sA[NPAIR];
    __shared__ ulonglong2 sB[NPAIR];
    __shared__ float wsum[TPB / 32];

    const int b = blockIdx.y;
    const float* Q = (blockIdx.z == 0) ? x1 : y1;
    const float* R = (blockIdx.z == 0) ? y1 : x1;
    const float* Qb = Q + (size_t)b * N_PTS * 3;
    const float* Rb = R + (size_t)b * N_PTS * 3;

    const int tid = threadIdx.x;
    const int p = blockIdx.x * TPB + tid;   // one query point per thread

    const float qx = Qb[p * 3 + 0];
    const float qy = Qb[p * 3 + 1];
    const float qz = Qb[p * 3 + 2];
    const float qsq = fmaf(qx, qx, fmaf(qy, qy, qz * qz));

    // duplicated query pairs (loop-invariant registers)
    const u64 qx2 = pack2(qx, qx);
    const u64 qy2 = pack2(qy, qy);
    const u64 qz2 = pack2(qz, qz);

    float mlo = CUDART_INF_F;   // min over even-lane candidates
    float mhi = CUDART_INF_F;   // min over odd-lane candidates

    for (int base = 0; base < N_PTS; base += TILE) {
        // cooperative tile fill: pack adjacent candidate pairs
        for (int k = tid; k < NPAIR; k += TPB) {
            const float* ra = Rb + (size_t)(base + 2 * k) * 3;
            const float ax = ra[0], ay = ra[1], az = ra[2];
            const float bx = ra[3], by = ra[4], bz = ra[5];
            const float asq = fmaf(ax, ax, fmaf(ay, ay, az * az));
            const float bsq = fmaf(bx, bx, fmaf(by, by, bz * bz));
            sA[k] = make_ulonglong2(pack2(-2.0f * ax, -2.0f * bx),
                                    pack2(-2.0f * ay, -2.0f * by));
            sB[k] = make_ulonglong2(pack2(-2.0f * az, -2.0f * bz),
                                    pack2(asq, bsq));
        }
        __syncthreads();

        #pragma unroll 8
        for (int k = 0; k < NPAIR; ++k) {
            const ulonglong2 a = sA[k];
            const ulonglong2 c = sB[k];
            // per candidate pair: d2' = c0*qx + c1*qy + c2*qz + cr  (3 FFMA2)
            u64 t = ffma2(c.x, qz2, c.y);
            t = ffma2(a.y, qy2, t);
            t = ffma2(a.x, qx2, t);
            const float2 f = unpack2(t);
            mlo = fminf(mlo, f.x);
            mhi = fminf(mhi, f.y);
        }
        __syncthreads();
    }

    const float m = fminf(mlo, mhi) + qsq;
    float v = sqrtf(fmaxf(m, 0.0f) + EPS);

    // warp reduce
    #pragma unroll
    for (int off = 16; off > 0; off >>= 1)
        v += __shfl_xor_sync(0xFFFFFFFFu, v, off);

    const int wid = tid >> 5;
    const int lid = tid & 31;
    if (lid == 0) wsum[wid] = v;
    __syncthreads();
    if (tid == 0) {
        float total = 0.0f;
        #pragma unroll
        for (int w = 0; w < TPB / 32; ++w) total += wsum[w];
        atomicAdd(out, total * scale);
    }
}

extern "C" void kernel_launch(void* const* d_in, const int* in_sizes, int n_in,
                              void* d_out, int out_size)
{
    const float* x1 = (const float*)d_in[0];
    const float* y1 = (const float*)d_in[1];
    float* out = (float*)d_out;

    zero_out_kernel<<<1, 1>>>(out);

    dim3 grid(N_PTS / TPB, B_DIM, 2);   // (32, 8, 2) = 512 blocks x 4 warps = 2048 warps
    const float scale = 1.0f / (float)(B_DIM * N_PTS);
    chamfer_kernel<<<grid, TPB>>>(x1, y1, out, scale);
}

// round 4
// speedup vs baseline: 1.4247x; 1.4247x over previous
#include <cuda_runtime.h>
#include <math_constants.h>

// ChamferLoss: B=8, N=M=4096, D=3, fp32 in, scalar fp32 out.
// d2' = -2*dot(q,r) + rsq   (qsq folded in AFTER the min)
// fma.rn.f32x2: 2 query points per FFMA2 (candidate coeffs duplicated in smem).
// PTS=8 queries/thread amortizes LDS (0.25 LDS/point-eval); 8 warps/block take
// disjoint candidate slices so total warps stay at 2048 (3.5/SMSP).

#define B_DIM  8
#define N_PTS  4096
#define TPB    256        // 8 warps
#define NSLICE 8          // one candidate slice per warp
#define PTS    8          // query points per thread (4 packed groups)
#define TILE   1024       // candidates per shared tile
#define SLICE  (TILE / NSLICE)   // 128 candidates per warp per tile
#define EPS    1e-8f

typedef unsigned long long u64;

__device__ __forceinline__ u64 ffma2(u64 a, u64 b, u64 c) {
    u64 d;
    asm("fma.rn.f32x2 %0, %1, %2, %3;" : "=l"(d) : "l"(a), "l"(b), "l"(c));
    return d;
}
__device__ __forceinline__ u64 pack2(float lo, float hi) {
    u64 d;
    asm("mov.b64 %0, {%1, %2};" : "=l"(d) : "f"(lo), "f"(hi));
    return d;
}
__device__ __forceinline__ float2 unpack2(u64 v) {
    float2 f;
    asm("mov.b64 {%0, %1}, %2;" : "=f"(f.x), "=f"(f.y) : "l"(v));
    return f;
}

__global__ void zero_out_kernel(float* out) { out[0] = 0.0f; }

__global__ __launch_bounds__(TPB) void chamfer_kernel(
    const float* __restrict__ x1, const float* __restrict__ y1,
    float* __restrict__ out, float scale)
{
    // sA[i] = { (-2rx,-2rx), (-2ry,-2ry) }   sB[i] = { (-2rz,-2rz), (rsq,rsq) }
    __shared__ ulonglong2 sA[TILE];
    __shared__ ulonglong2 sB[TILE];
    __shared__ float sPart[NSLICE][TPB];   // [slice][q_local] partial mins
    __shared__ float sQsq[TPB];
    __shared__ float wsum[TPB / 32];

    const int b = blockIdx.y;
    const float* Q = (blockIdx.z == 0) ? x1 : y1;
    const float* R = (blockIdx.z == 0) ? y1 : x1;
    const float* Qb = Q + (size_t)b * N_PTS * 3;
    const float* Rb = R + (size_t)b * N_PTS * 3;

    const int tid = threadIdx.x;
    const int u   = tid & 31;    // lane: query sub-id
    const int s   = tid >> 5;    // warp: candidate slice
    const int qbase = blockIdx.x * TPB;   // 256 queries per block

    // 8 query points per thread: q_local = u + k*32 (same for every warp)
    float qx[PTS], qy[PTS], qz[PTS], qsq[PTS];
    #pragma unroll
    for (int k = 0; k < PTS; ++k) {
        const int p = qbase + u + k * 32;
        qx[k] = Qb[p * 3 + 0];
        qy[k] = Qb[p * 3 + 1];
        qz[k] = Qb[p * 3 + 2];
        qsq[k] = fmaf(qx[k], qx[k], fmaf(qy[k], qy[k], qz[k] * qz[k]));
    }
    // packed query registers: group g = points (2g, 2g+1)
    u64 qX[4], qY[4], qZ[4];
    #pragma unroll
    for (int g = 0; g < 4; ++g) {
        qX[g] = pack2(qx[2 * g], qx[2 * g + 1]);
        qY[g] = pack2(qy[2 * g], qy[2 * g + 1]);
        qZ[g] = pack2(qz[2 * g], qz[2 * g + 1]);
    }

    float mn[PTS];
    #pragma unroll
    for (int k = 0; k < PTS; ++k) mn[k] = CUDART_INF_F;

    for (int base = 0; base < N_PTS; base += TILE) {
        // cooperative tile fill (4 candidates per thread)
        for (int i = tid; i < TILE; i += TPB) {
            const float* r = Rb + (size_t)(base + i) * 3;
            const float rx = r[0], ry = r[1], rz = r[2];
            const float rq = fmaf(rx, rx, fmaf(ry, ry, rz * rz));
            const float c0 = -2.0f * rx, c1 = -2.0f * ry, c2 = -2.0f * rz;
            sA[i] = make_ulonglong2(pack2(c0, c0), pack2(c1, c1));
            sB[i] = make_ulonglong2(pack2(c2, c2), pack2(rq, rq));
        }
        __syncthreads();

        // this warp's candidate slice within the tile
        const ulonglong2* __restrict__ pA = sA + s * SLICE;
        const ulonglong2* __restrict__ pB = sB + s * SLICE;

        #pragma unroll 4
        for (int j = 0; j < SLICE; ++j) {
            const ulonglong2 a = pA[j];   // (c0,c0),(c1,c1)
            const ulonglong2 c = pB[j];   // (c2,c2),(cr,cr)
            #pragma unroll
            for (int g = 0; g < 4; ++g) {
                u64 t = ffma2(c.x, qZ[g], c.y);
                t = ffma2(a.y, qY[g], t);
                t = ffma2(a.x, qX[g], t);
                const float2 f = unpack2(t);
                mn[2 * g]     = fminf(mn[2 * g],     f.x);
                mn[2 * g + 1] = fminf(mn[2 * g + 1], f.y);
            }
        }
        __syncthreads();
    }

    // publish partial mins; warp 0 publishes qsq
    #pragma unroll
    for (int k = 0; k < PTS; ++k) sPart[s][u + k * 32] = mn[k];
    if (s == 0) {
        #pragma unroll
        for (int k = 0; k < PTS; ++k) sQsq[u + k * 32] = qsq[k];
    }
    __syncthreads();

    // combine slices: thread tid owns query q_local = tid
    float m = sPart[0][tid];
    #pragma unroll
    for (int ss = 1; ss < NSLICE; ++ss) m = fminf(m, sPart[ss][tid]);
    float v = sqrtf(fmaxf(m + sQsq[tid], 0.0f) + EPS);

    // block sum
    #pragma unroll
    for (int off = 16; off > 0; off >>= 1)
        v += __shfl_xor_sync(0xFFFFFFFFu, v, off);
    if (u == 0) wsum[s] = v;
    __syncthreads();
    if (tid == 0) {
        float total = 0.0f;
        #pragma unroll
        for (int w = 0; w < TPB / 32; ++w) total += wsum[w];
        atomicAdd(out, total * scale);
    }
}

extern "C" void kernel_launch(void* const* d_in, const int* in_sizes, int n_in,
                              void* d_out, int out_size)
{
    const float* x1 = (const float*)d_in[0];
    const float* y1 = (const float*)d_in[1];
    float* out = (float*)d_out;

    zero_out_kernel<<<1, 1>>>(out);

    dim3 grid(N_PTS / TPB, B_DIM, 2);   // (16, 8, 2) = 256 blocks x 8 warps = 2048 warps
    const float scale = 1.0f / (float)(B_DIM * N_PTS);
    chamfer_kernel<<<grid, TPB>>>(x1, y1, out, scale);
}